// round 12
// baseline (speedup 1.0000x reference)
#include <cuda_runtime.h>
#include <math.h>
#include <stdint.h>

#define STEPS   30
#define NBINS   31
#define THREADS 512
#define WARPS   (THREADS / 32)     // 16
#define GRID    592                // 148 SMs * 4 CTAs (512thr) -> 64 warps/SM
#define NREP    8
#define TILE4   1024               // float4s per tile (16 KB)
#define TILE_B  (TILE4 * 16)
#define STAGES  3

// smem layout (dynamic)
#define SM_BUF   0
#define SM_MBAR  (STAGES * TILE_B)                  // 49152, 8B aligned
#define SM_ALL   (SM_MBAR + 64)
#define SM_TRU   (SM_ALL + WARPS * 32 * 4)
#define SM_FIN   (SM_TRU + WARPS * 32 * 4)
#define SM_TOTAL (SM_FIN + 64 * 4 + 16)

// Zero at module load; last block reads and re-zeroes each launch.
__device__ unsigned int g_hist[NREP][64];
__device__ unsigned int g_done;

extern __shared__ __align__(128) unsigned char smem[];

__device__ __forceinline__ uint32_t smem_u32(const void* p) {
    uint32_t a;
    asm("{ .reg .u64 t; cvta.to.shared.u64 t, %1; cvt.u32.u64 %0, t; }" : "=r"(a) : "l"(p));
    return a;
}
__device__ __forceinline__ float fast_tanh(float x) {
    float r; asm("tanh.approx.f32 %0, %1;" : "=f"(r) : "f"(x)); return r;
}
__device__ __forceinline__ int bin_of(float x) {
    float t = fast_tanh(0.5f * x);
    return (int)fmaf(t, 15.0f, 15.0f);     // floor(30*sigmoid(x)), in [0,30]
}
__device__ __forceinline__ void mbar_init(uint32_t mb, uint32_t cnt) {
    asm volatile("mbarrier.init.shared.b64 [%0], %1;" :: "r"(mb), "r"(cnt) : "memory");
}
__device__ __forceinline__ void mbar_expect_tx(uint32_t mb, uint32_t bytes) {
    asm volatile("mbarrier.arrive.expect_tx.shared.b64 _, [%0], %1;" :: "r"(mb), "r"(bytes) : "memory");
}
__device__ __forceinline__ void bulk_g2s(uint32_t dst, const void* src, uint32_t bytes, uint32_t mb) {
    asm volatile("cp.async.bulk.shared::cluster.global.mbarrier::complete_tx::bytes [%0], [%1], %2, [%3];"
                 :: "r"(dst), "l"(src), "r"(bytes), "r"(mb) : "memory");
}
__device__ __forceinline__ void mbar_wait(uint32_t mb, uint32_t parity) {
    uint32_t done;
    asm volatile("{\n\t.reg .pred p;\n\t"
                 "mbarrier.try_wait.parity.acquire.cta.shared::cta.b64 p, [%1], %2;\n\t"
                 "selp.b32 %0, 1, 0, p;\n\t}"
                 : "=r"(done) : "r"(mb), "r"(parity) : "memory");
    if (!done) {
        asm volatile("{\n\t.reg .pred P1;\n\t"
                     "W_%=:\n\t"
                     "mbarrier.try_wait.parity.acquire.cta.shared::cta.b64 P1, [%0], %1, 0x989680;\n\t"
                     "@P1 bra.uni D_%=;\n\t"
                     "bra.uni W_%=;\n\t"
                     "D_%=:\n\t}"
                     :: "r"(mb), "r"(parity) : "memory");
    }
}

__global__ void __launch_bounds__(THREADS) auc_kernel(
    const float* __restrict__ gsrc, const int* __restrict__ tgt,
    int n4, int N, int C, float* __restrict__ out)
{
    unsigned int* s_all = (unsigned int*)(smem + SM_ALL);   // [WARPS][32]
    unsigned int* s_tru = (unsigned int*)(smem + SM_TRU);   // [WARPS][32]
    unsigned int* s_fin = (unsigned int*)(smem + SM_FIN);   // [64]

    const int tid  = threadIdx.x;
    const int wid  = tid >> 5;
    const int lane = tid & 31;
    const int bid  = blockIdx.x;

    s_all[wid * 32 + lane] = 0u;
    s_tru[wid * 32 + lane] = 0u;
    if (tid == 0) {
        #pragma unroll
        for (int s = 0; s < STAGES; s++)
            mbar_init(smem_u32(smem + SM_MBAR) + s * 8, 1u);
    }
    __syncthreads();

    const uint32_t mbar0 = smem_u32(smem + SM_MBAR);
    const uint32_t buf0  = smem_u32(smem + SM_BUF);

    const int ntt = (n4 + TILE4 - 1) / TILE4;                       // 7813
    const int nt  = (bid < ntt) ? (ntt - bid + GRID - 1) / GRID : 0;

    // prologue: fill the pipeline
    if (tid == 0) {
        int np = nt < STAGES ? nt : STAGES;
        for (int s = 0; s < np; s++) {
            int t      = bid + s * GRID;
            int start4 = t * TILE4;
            uint32_t bytes = (uint32_t)(min(TILE4, n4 - start4)) * 16u;
            mbar_expect_tx(mbar0 + s * 8, bytes);
            bulk_g2s(buf0 + s * TILE_B, (const char*)gsrc + (size_t)start4 * 16, bytes, mbar0 + s * 8);
        }
    }

    for (int k = 0; k < nt; k++) {
        const int s  = k % STAGES;
        const int ph = (k / STAGES) & 1;
        mbar_wait(mbar0 + s * 8, (uint32_t)ph);

        const int t      = bid + k * GRID;
        const int start4 = t * TILE4;
        const int cnt4   = min(TILE4, n4 - start4);
        const float4* buf = (const float4*)(smem + SM_BUF + s * TILE_B);

        #pragma unroll
        for (int h = 0; h < TILE4 / THREADS; h++) {
            int j = tid + h * THREADS;
            if (j < cnt4) {
                float4 v = buf[j];
                int i4   = start4 + j;
                int tcol = __ldg(tgt + (i4 >> 4));          // C==64: 16 float4/row
                int jt   = tcol - ((i4 & 15) << 2);

                int b0 = bin_of(v.x);
                int b1 = bin_of(v.y);
                int b2 = bin_of(v.z);
                int b3 = bin_of(v.w);

                atomicAdd(&s_all[wid * 32 + b0], 1u);
                atomicAdd(&s_all[wid * 32 + b1], 1u);
                atomicAdd(&s_all[wid * 32 + b2], 1u);
                atomicAdd(&s_all[wid * 32 + b3], 1u);

                if ((unsigned)jt < 4u) {
                    int bt = (jt == 0) ? b0 : (jt == 1) ? b1 : (jt == 2) ? b2 : b3;
                    atomicAdd(&s_tru[wid * 32 + bt], 1u);
                }
            }
        }
        __syncthreads();                       // stage s fully consumed

        if (tid == 0) {
            int kn = k + STAGES;
            if (kn < nt) {
                int t2      = bid + kn * GRID;
                int start42 = t2 * TILE4;
                uint32_t bytes = (uint32_t)(min(TILE4, n4 - start42)) * 16u;
                mbar_expect_tx(mbar0 + s * 8, bytes);
                bulk_g2s(buf0 + s * TILE_B, (const char*)gsrc + (size_t)start42 * 16, bytes, mbar0 + s * 8);
            }
        }
    }
    __syncthreads();

    // fold warps -> global replicated histograms
    const int rep = bid & (NREP - 1);
    if (tid < NBINS) {
        unsigned a = 0u;
        #pragma unroll
        for (int w = 0; w < WARPS; w++) a += s_all[w * 32 + tid];
        atomicAdd(&g_hist[rep][tid], a);
    } else if (tid >= 32 && tid < 32 + NBINS) {
        int kk = tid - 32;
        unsigned tcnt = 0u;
        #pragma unroll
        for (int w = 0; w < WARPS; w++) tcnt += s_tru[w * 32 + kk];
        atomicAdd(&g_hist[rep][32 + kk], tcnt);
    }

    // ---- last-block epilogue ----
    __threadfence();
    __shared__ unsigned int s_last;
    if (tid == 0) s_last = (atomicAdd(&g_done, 1u) == GRID - 1) ? 1u : 0u;
    __syncthreads();
    if (!s_last) return;

    __threadfence();
    if (tid < 64) {
        unsigned acc = 0u;
        #pragma unroll
        for (int r = 0; r < NREP; r++) acc += g_hist[r][tid];
        s_fin[tid] = acc;
        #pragma unroll
        for (int r = 0; r < NREP; r++) g_hist[r][tid] = 0u;
    }
    if (tid == 0) g_done = 0u;
    __syncthreads();

    if (tid < 32) {
        const unsigned full = 0xffffffffu;
        const bool act = lane < STEPS;

        double ht = act ? (double)s_fin[32 + lane] : 0.0;
        double hf = act ? ((double)s_fin[lane] - (double)s_fin[32 + lane]) : 0.0;

        double ct = ht, cf = hf;
        #pragma unroll
        for (int d = 1; d < 32; d <<= 1) {
            double ut = __shfl_up_sync(full, ct, d);
            double uf = __shfl_up_sync(full, cf, d);
            if (lane >= d) { ct += ut; cf += uf; }
        }

        const double trues_sum  = (double)N;
        const double total      = (double)N * (double)C;
        const double falses_sum = total - trues_sum;
        const double EPS = 1e-8;
        const double inv_t = 1.0 / (trues_sum + EPS);
        const double inv_f = 1.0 / (falses_sum + EPS);

        double tpr = (trues_sum  - ct) * inv_t;
        double fpr = (falses_sum - cf) * inv_f;

        double tpr_n = __shfl_down_sync(full, tpr, 1);
        double fpr_n = __shfl_down_sync(full, fpr, 1);
        if (lane >= STEPS - 1) { tpr_n = 0.0; fpr_n = 0.0; }

        double term = 0.0;
        if (act) {
            double w    = fabs(fpr - fpr_n);
            double tmin = fmin(tpr, tpr_n);
            double tmax = fmax(tpr, tpr_n);
            term = w * tmin + 0.5 * w * (tmax - tmin);
        }
        #pragma unroll
        for (int d = 16; d > 0; d >>= 1)
            term += __shfl_xor_sync(full, term, d);

        if (lane == 0) out[0] = (float)term;
    }
}

extern "C" void kernel_launch(void* const* d_in, const int* in_sizes, int n_in,
                              void* d_out, int out_size)
{
    const float* output = (const float*)d_in[0];
    const int*   target = (const int*)d_in[1];
    int total = in_sizes[0];      // N*C = 32,000,000
    int N     = in_sizes[1];      // 500,000
    int C     = total / N;        // 64
    int n4    = total >> 2;

    // Idempotent, immediate (not a stream op) -> safe to call every time,
    // including on the graph-capture call.
    cudaFuncSetAttribute(auc_kernel, cudaFuncAttributeMaxDynamicSharedMemorySize, SM_TOTAL);
    auc_kernel<<<GRID, THREADS, SM_TOTAL>>>(output, target, n4, N, C, (float*)d_out);
}

// round 13
// speedup vs baseline: 1.2521x; 1.2521x over previous
#include <cuda_runtime.h>
#include <math.h>

#define STEPS   30
#define NBINS   31
#define THREADS 256
#define WARPS   (THREADS / 32)
#define GRID    1184           // 148 SMs * 8 CTAs -> 64 warps/SM, single wave
#define NREP    8              // global histogram replicas

// Zero at module load; the last block reads and re-zeroes them each launch,
// so every graph replay (and the correctness run) starts from zero state.
__device__ unsigned int g_hist[NREP][64];   // [r][0..30]=all, [r][32..62]=true
__device__ unsigned int g_done;

__device__ __forceinline__ float fast_tanh(float x) {
    float r; asm("tanh.approx.f32 %0, %1;" : "=f"(r) : "f"(x)); return r;
}

__device__ __forceinline__ int bin_of(float x) {
    // sigmoid(x) = 0.5*tanh(x/2)+0.5 ; bin = floor(30*s) = floor(15*tanh+15)
    float t = fast_tanh(0.5f * x);
    return (int)fmaf(t, 15.0f, 15.0f);     // in [0,30]
}

__global__ void __launch_bounds__(THREADS) auc_kernel(
    const float4* __restrict__ out4, const float* __restrict__ gsrc,
    const int* __restrict__ tgt,
    int n4, int N, int C, float* __restrict__ out)
{
    __shared__ unsigned int s_all[WARPS][32];
    __shared__ unsigned int s_tru[WARPS][32];
    __shared__ unsigned int s_fin[64];
    __shared__ unsigned int s_last;

    const int tid  = threadIdx.x;
    const int wid  = tid >> 5;
    const int lane = tid & 31;

    s_all[wid][lane] = 0u;
    s_tru[wid][lane] = 0u;
    __syncthreads();

    const int gid    = blockIdx.x * THREADS + tid;
    const int stride = GRID * THREADS;

    // ---- phase 1: true-class gather (one element per row) ----
    for (int r = gid; r < N; r += stride) {
        int   tcol = __ldg(tgt + r);
        float x    = __ldg(gsrc + (size_t)r * C + tcol);
        atomicAdd(&s_tru[wid][bin_of(x)], 1u);
    }

    // ---- phase 2: all-elements histogram (no target logic) ----
    #pragma unroll 4
    for (int i4 = gid; i4 < n4; i4 += stride) {
        float4 v = out4[i4];
        int b0 = bin_of(v.x);
        int b1 = bin_of(v.y);
        int b2 = bin_of(v.z);
        int b3 = bin_of(v.w);
        atomicAdd(&s_all[wid][b0], 1u);
        atomicAdd(&s_all[wid][b1], 1u);
        atomicAdd(&s_all[wid][b2], 1u);
        atomicAdd(&s_all[wid][b3], 1u);
    }
    __syncthreads();

    // fold 8 warps -> global replicated histograms
    const int rep = blockIdx.x & (NREP - 1);
    if (tid < NBINS) {
        unsigned a = 0u;
        #pragma unroll
        for (int w = 0; w < WARPS; w++) a += s_all[w][tid];
        atomicAdd(&g_hist[rep][tid], a);
    } else if (tid >= 32 && tid < 32 + NBINS) {
        int k = tid - 32;
        unsigned t = 0u;
        #pragma unroll
        for (int w = 0; w < WARPS; w++) t += s_tru[w][k];
        atomicAdd(&g_hist[rep][32 + k], t);
    }

    // ---- last-block epilogue ----
    __threadfence();
    if (tid == 0) s_last = (atomicAdd(&g_done, 1u) == GRID - 1) ? 1u : 0u;
    __syncthreads();
    if (!s_last) return;

    __threadfence();                                // see all blocks' atomics
    if (tid < 64) {
        unsigned acc = 0u;
        #pragma unroll
        for (int r = 0; r < NREP; r++) acc += g_hist[r][tid];
        s_fin[tid] = acc;
        #pragma unroll
        for (int r = 0; r < NREP; r++) g_hist[r][tid] = 0u;   // clean for next replay
    }
    if (tid == 0) g_done = 0u;
    __syncthreads();

    if (tid < 32) {
        const unsigned full = 0xffffffffu;
        const bool act = lane < STEPS;

        double ht = act ? (double)s_fin[32 + lane] : 0.0;
        double hf = act ? ((double)s_fin[lane] - (double)s_fin[32 + lane]) : 0.0;

        // inclusive scan: cumsum of hist_t / hist_f over ascending bins
        double ct = ht, cf = hf;
        #pragma unroll
        for (int d = 1; d < 32; d <<= 1) {
            double ut = __shfl_up_sync(full, ct, d);
            double uf = __shfl_up_sync(full, cf, d);
            if (lane >= d) { ct += ut; cf += uf; }
        }

        const double trues_sum  = (double)N;
        const double total      = (double)N * (double)C;
        const double falses_sum = total - trues_sum;
        const double EPS = 1e-8;
        const double inv_t = 1.0 / (trues_sum + EPS);
        const double inv_f = 1.0 / (falses_sum + EPS);

        double tpr = (trues_sum  - ct) * inv_t;
        double fpr = (falses_sum - cf) * inv_f;

        double tpr_n = __shfl_down_sync(full, tpr, 1);
        double fpr_n = __shfl_down_sync(full, fpr, 1);
        if (lane >= STEPS - 1) { tpr_n = 0.0; fpr_n = 0.0; }

        double term = 0.0;
        if (act) {
            double w    = fabs(fpr - fpr_n);
            double tmin = fmin(tpr, tpr_n);
            double tmax = fmax(tpr, tpr_n);
            term = w * tmin + 0.5 * w * (tmax - tmin);
        }

        #pragma unroll
        for (int d = 16; d > 0; d >>= 1)
            term += __shfl_xor_sync(full, term, d);

        if (lane == 0) out[0] = (float)term;
    }
}

extern "C" void kernel_launch(void* const* d_in, const int* in_sizes, int n_in,
                              void* d_out, int out_size)
{
    const float* output = (const float*)d_in[0];
    const int*   target = (const int*)d_in[1];
    int total = in_sizes[0];      // N*C = 32,000,000
    int N     = in_sizes[1];      // 500,000
    int C     = total / N;        // 64
    int n4    = total >> 2;

    auc_kernel<<<GRID, THREADS>>>((const float4*)output, output, target,
                                  n4, N, C, (float*)d_out);
}